// round 9
// baseline (speedup 1.0000x reference)
#include <cuda_runtime.h>
#include <cuda_fp16.h>
#include <math.h>

// Problem constants: B=2, L=1024, E=1024, H=8, D=64, N_ITERS=20
#define NBH   16
#define LSEQ  1024
#define DH    64
#define EDIM  1024
#define HD    512
#define MROWS 2048
#define NITERS 20
#define NBLOCKS 148
#define MAXROWS 111
#define NR_TOT  16384

// SMEM layout of sinkhorn_tc (bytes)
#define PS_BYTES (MAXROWS * 2048)          // 227328
#define USF_OFF  PS_BYTES                  // float[112] row sums
#define UNI_OFF  (USF_OFF + 448)           // union: vsh h[2][1024] / ush0,ush1 h[128]
#define SMEM_SZ  (UNI_OFF + 4096)          // 231872 <= 232448

// ---------------- scratch (device globals) ----------------
__device__ __half g_xh [MROWS * EDIM];
__device__ __half g_wh [3 * HD * EDIM];
__device__ __half g_woh[EDIM * HD];
__device__ __half g_qh [NR_TOT * DH];
__device__ __half g_kh [NR_TOT * DH];
__device__ float  g_v  [NR_TOT * DH];
__device__ __half g_vt [NBH * DH * LSEQ];
__device__ __half g_P  [NBH * LSEQ * LSEQ];
__device__ __half g_ah [MROWS * HD];
__device__ float  g_ur [NBH * LSEQ];
__device__ float  g_part[2][NBLOCKS][2][1024];   // partial colsums (dbl buffered)
__device__ unsigned g_flags[NBLOCKS];
__device__ volatile unsigned g_gen;

// ---------------- helpers ----------------
__device__ __forceinline__ int row_start(int b) {
    return (b < 104) ? b * 111 : 11544 + (b - 104) * 110;
}
__device__ __forceinline__ int blk_of(int row) {
    return (row < 11544) ? row / 111 : 104 + (row - 11544) / 110;
}
__device__ __forceinline__ void ldsm4(unsigned& r0, unsigned& r1,
                                      unsigned& r2, unsigned& r3, unsigned addr) {
    asm volatile("ldmatrix.sync.aligned.m8n8.x4.shared.b16 {%0,%1,%2,%3},[%4];\n"
                 : "=r"(r0), "=r"(r1), "=r"(r2), "=r"(r3) : "r"(addr));
}
__device__ __forceinline__ void ldsm4t(unsigned& r0, unsigned& r1,
                                       unsigned& r2, unsigned& r3, unsigned addr) {
    asm volatile("ldmatrix.sync.aligned.m8n8.x4.trans.shared.b16 {%0,%1,%2,%3},[%4];\n"
                 : "=r"(r0), "=r"(r1), "=r"(r2), "=r"(r3) : "r"(addr));
}
__device__ __forceinline__ void mma16816(float* c, const unsigned* a,
                                         unsigned b0, unsigned b1) {
    asm volatile(
        "mma.sync.aligned.m16n8k16.row.col.f32.f16.f16.f32 "
        "{%0,%1,%2,%3},{%4,%5,%6,%7},{%8,%9},{%0,%1,%2,%3};\n"
        : "+f"(c[0]), "+f"(c[1]), "+f"(c[2]), "+f"(c[3])
        : "r"(a[0]), "r"(a[1]), "r"(a[2]), "r"(a[3]), "r"(b0), "r"(b1));
}
__device__ __forceinline__ unsigned sw_off(int row, int chunk) {
    return (unsigned)(row * 2048 + ((chunk ^ (row & 7)) << 4));
}
__device__ __forceinline__ unsigned packh2(float a, float b) {
    __half2 h = __floats2half2_rn(a, b);
    return *(unsigned*)&h;
}
__device__ __forceinline__ void cp16(void* smem_dst, const void* gsrc) {
    unsigned d = (unsigned)__cvta_generic_to_shared(smem_dst);
    asm volatile("cp.async.ca.shared.global [%0], [%1], 16;\n" :: "r"(d), "l"(gsrc));
}
__device__ __forceinline__ void cp_commit() {
    asm volatile("cp.async.commit_group;\n");
}
template <int N> __device__ __forceinline__ void cp_wait() {
    asm volatile("cp.async.wait_group %0;\n" :: "n"(N));
}

// flag-based grid barrier: contention-free arrival, leader(block 0) release
__device__ __forceinline__ void gsync_flag(int it) {
    __syncthreads();
    __threadfence();                       // drain partial STGs
    if (threadIdx.x == 0)
        *(volatile unsigned*)&g_flags[blockIdx.x] = (unsigned)(it + 1);
    if (blockIdx.x == 0) {
        if (threadIdx.x < NBLOCKS) {
            while (*(volatile unsigned*)&g_flags[threadIdx.x] < (unsigned)(it + 1))
                __nanosleep(64);
        }
        __syncthreads();
        if (threadIdx.x == 0) { __threadfence(); g_gen = (unsigned)(it + 1); }
    } else {
        if (threadIdx.x == 0) {
            while (g_gen < (unsigned)(it + 1)) __nanosleep(64);
        }
        __syncthreads();
    }
    __threadfence();                       // acquire: L1 invalidate
}

// ============================================================================
// 128x64 block HMMA GEMM with 2-stage cp.async pipeline (unchanged from R8).
// ============================================================================
template <class Epi>
__device__ __forceinline__ void hgemm(const __half* __restrict__ A,
                                      const __half* __restrict__ Bn,
                                      int K, int m0, int n0, Epi epi)
{
    __shared__ __half As[2][128 * 40];
    __shared__ __half Bs[2][64 * 40];

    const int tid  = threadIdx.x;
    const int lane = tid & 31, warp = tid >> 5;
    const int wm = warp & 3, wn = warp >> 2;

    const int arow = tid >> 1, acol = (tid & 1) * 16;
    const int brow = tid >> 2, bcol = (tid & 3) * 8;
    const __half* Ag = A  + (m0 + arow) * K + acol;
    const __half* Bg = Bn + (n0 + brow) * K + bcol;

    float acc[2][4][4] = {};

    const unsigned a_off0 = (unsigned)__cvta_generic_to_shared(
        &As[0][(wm * 32 + 0  + (lane & 15)) * 40 + ((lane >> 4) << 3)]);
    const unsigned a_off1 = (unsigned)__cvta_generic_to_shared(
        &As[0][(wm * 32 + 16 + (lane & 15)) * 40 + ((lane >> 4) << 3)]);
    const unsigned abuf = 128 * 40 * 2;

    cp16(&As[0][arow * 40 + acol],     Ag);
    cp16(&As[0][arow * 40 + acol + 8], Ag + 8);
    cp16(&Bs[0][brow * 40 + bcol],     Bg);
    cp_commit();

    const int KT = K >> 5;
    for (int kt = 0; kt < KT; kt++) {
        const int buf = kt & 1;
        if (kt + 1 < KT) {
            const int nb = buf ^ 1;
            cp16(&As[nb][arow * 40 + acol],     Ag + (kt + 1) * 32);
            cp16(&As[nb][arow * 40 + acol + 8], Ag + (kt + 1) * 32 + 8);
            cp16(&Bs[nb][brow * 40 + bcol],     Bg + (kt + 1) * 32);
            cp_commit();
            cp_wait<1>();
        } else {
            cp_wait<0>();
        }
        __syncthreads();

        #pragma unroll
        for (int s = 0; s < 2; s++) {
            unsigned a0[4], a1[4];
            ldsm4(a0[0], a0[1], a0[2], a0[3], a_off0 + buf * abuf + s * 32);
            ldsm4(a1[0], a1[1], a1[2], a1[3], a_off1 + buf * abuf + s * 32);
            #pragma unroll
            for (int j = 0; j < 4; j++) {
                const __half* bp2 =
                    &Bs[buf][(wn * 32 + j * 8 + (lane >> 2)) * 40 + s * 16 + (lane & 3) * 2];
                unsigned b0 = *(const unsigned*)bp2;
                unsigned b1 = *(const unsigned*)(bp2 + 8);
                mma16816(acc[0][j], a0, b0, b1);
                mma16816(acc[1][j], a1, b0, b1);
            }
        }
        __syncthreads();
    }

    const int g = lane >> 2, c2 = (lane & 3) * 2;
    #pragma unroll
    for (int f = 0; f < 2; f++)
        #pragma unroll
        for (int j = 0; j < 4; j++) {
            int rm = m0 + wm * 32 + f * 16 + g;
            int cn = n0 + wn * 32 + j * 8 + c2;
            epi(rm,     cn, acc[f][j][0], acc[f][j][1]);
            epi(rm + 8, cn, acc[f][j][2], acc[f][j][3]);
        }
}

// ---------------- epilogues ----------------
struct EpiQKV {
    const float* bias; int z;
    __device__ void operator()(int m, int n, float v0, float v1) const {
        int b = m >> 10, l = m & 1023, h = n >> 6, d = n & 63;
        int idx = (((b << 3) + h) << 16) + (l << 6) + d;
        float a0 = v0 + bias[n], a1 = v1 + bias[n + 1];
        if (z == 0)      *(unsigned*)(g_qh + idx) = packh2(a0, a1);
        else if (z == 1) *(unsigned*)(g_kh + idx) = packh2(a0, a1);
        else             { float2 f2 = {a0, a1}; *(float2*)(g_v + idx) = f2; }
    }
};
struct EpiP {
    __half* P;
    __device__ void operator()(int m, int n, float v0, float v1) const {
        *(unsigned*)(P + m * LSEQ + n) =
            packh2(__expf(v0 * 0.125f), __expf(v1 * 0.125f));
    }
};
struct EpiAttnV {
    int bh;
    __device__ void operator()(int m, int n, float v0, float v1) const {
        float u = g_ur[(bh << 10) + m];
        int b = bh >> 3, h = bh & 7;
        *(unsigned*)(g_ah + (b * LSEQ + m) * HD + h * DH + n) =
            packh2(u * v0, u * v1);
    }
};
struct EpiOut {
    const float* bo; float* out;
    __device__ void operator()(int m, int n, float v0, float v1) const {
        float2 f2 = {v0 + bo[n], v1 + bo[n + 1]};
        *(float2*)(out + m * EDIM + n) = f2;
    }
};

// ---------------- GEMM kernels ----------------
__global__ __launch_bounds__(256) void qkv_h_kernel(
    const float* __restrict__ bq, const float* __restrict__ bk,
    const float* __restrict__ bv)
{
    const int z = blockIdx.z;
    const float* bias = (z == 0) ? bq : (z == 1) ? bk : bv;
    EpiQKV epi{bias, z};
    hgemm(g_xh, g_wh + z * (HD * EDIM), EDIM,
          blockIdx.y * 128, blockIdx.x * 64, epi);
}
__global__ __launch_bounds__(256) void p_h_kernel()
{
    const int bh = blockIdx.z;
    EpiP epi{g_P + ((size_t)bh << 20)};
    hgemm(g_qh + (bh << 16), g_kh + (bh << 16), DH,
          blockIdx.y * 128, blockIdx.x * 64, epi);
}
__global__ __launch_bounds__(256) void attnv_h_kernel()
{
    const int bh = blockIdx.z;
    EpiAttnV epi{bh};
    hgemm(g_P + ((size_t)bh << 20), g_vt + (bh << 16), LSEQ,
          blockIdx.y * 128, blockIdx.x * 64, epi);
}
__global__ __launch_bounds__(256) void out_h_kernel(
    const float* __restrict__ bo, float* __restrict__ out)
{
    EpiOut epi{bo, out};
    hgemm(g_ah, g_woh, HD, blockIdx.y * 128, blockIdx.x * 64, epi);
}

// ============================================================================
// fused conversions + barrier-state reset.  grid 6145 x 256.
// ============================================================================
__global__ __launch_bounds__(256) void conv_all(
    const float* __restrict__ x,
    const float* __restrict__ Wq, const float* __restrict__ Wk,
    const float* __restrict__ Wv, const float* __restrict__ Wo)
{
    __shared__ float t[32][33];
    const int b = blockIdx.x;
    const int tid = threadIdx.x;

    if (b < 2048) {
        int idx = b * 256 + tid;
        float4 v = ((const float4*)x)[idx];
        ((__half2*)g_xh)[2 * idx]     = __floats2half2_rn(v.x, v.y);
        ((__half2*)g_xh)[2 * idx + 1] = __floats2half2_rn(v.z, v.w);
    } else if (b < 6144) {
        const int bb = b - 2048;
        const int z = bb >> 10, rem = bb & 1023;
        const float* src; __half* dst; int R, C;
        if (z < 3) { src = (z == 0) ? Wq : (z == 1) ? Wk : Wv;
                     dst = g_wh + z * (HD * EDIM); R = 1024; C = 512; }
        else       { src = Wo; dst = g_woh; R = 512; C = 1024; }
        const int r0 = (rem >> 5) * 32, c0 = (rem & 31) * 32;
        if (r0 < R && c0 < C) {
            const int tx = tid & 31, ty = tid >> 5;
            for (int r = ty; r < 32; r += 8)
                t[r][tx] = src[(r0 + r) * C + c0 + tx];
            __syncthreads();
            for (int r = ty; r < 32; r += 8)
                dst[(c0 + r) * R + r0 + tx] = __float2half_rn(t[tx][r]);
        }
    } else {
        if (tid < NBLOCKS) g_flags[tid] = 0;
        if (tid == 200) g_gen = 0;
    }
}

// ============================================================================
// Persistent Sinkhorn v3: tensor-core phases, atomic-free partial-sum
// exchange, flag barrier.  grid 148, block 1024.
// ============================================================================
__global__ __launch_bounds__(1024, 1) void sinkhorn_tc()
{
    extern __shared__ char smem[];
    char*   PsB  = smem;
    float*  us_f = (float*)(smem + USF_OFF);          // [112] row sums
    __half* vsh  = (__half*)(smem + UNI_OFF);         // [2][1024] during row
    __half* ush0 = (__half*)(smem + UNI_OFF);         // after row phase
    __half* ush1 = (__half*)(smem + UNI_OFF + 256);
    const unsigned ps_base = (unsigned)__cvta_generic_to_shared(PsB);

    const int blk = blockIdx.x;
    const int r0 = row_start(blk), r1 = row_start(blk + 1);
    const int nrows = r1 - r0;
    const int tid = threadIdx.x;
    const int warp = tid >> 5, lane = tid & 31;
    const int g = lane >> 2, c2 = (lane & 3) * 2;
    const int l15 = lane & 15, l16 = lane >> 4;

    const int bh0 = r0 >> 10;
    const int s_break = min(nrows, ((bh0 + 1) << 10) - r0);
    const int nseg = (s_break < nrows) ? 2 : 1;
    const int mt = warp >> 2;
    const int kq = warp & 3;

    // ---- load P slice (row-major global -> swizzled SMEM), once ----
    for (int idx = tid; idx < nrows * 128; idx += 1024) {
        int row = idx >> 7, chunk = idx & 127;
        uint4 v = *(const uint4*)(g_P + ((size_t)(r0 + row) << 10) + chunk * 8);
        *(uint4*)(PsB + sw_off(row, chunk)) = v;
    }
    __syncthreads();

    const __half one_h = __float2half_rn(1.0f);

    for (int it = 0; it < NITERS; it++) {
        const int rbuf = (it + 1) & 1;     // partials written at it-1
        const int wbuf = it & 1;

        // ---- stage v (both segments) + zero row sums ----
        if (it == 0) {
            vsh[tid] = one_h;
            if (nseg == 2) vsh[1024 + tid] = one_h;
        } else {
            for (int s = 0; s < nseg; s++) {
                const int bh = bh0 + s;
                const int b_lo = blk_of(bh << 10);
                const int b_hi = blk_of((bh << 10) + 1023);
                float sum = 0.0f;
                for (int b2 = b_lo; b2 <= b_hi; b2++) {
                    const int s2 = ((row_start(b2) >> 10) == bh) ? 0 : 1;
                    sum += g_part[rbuf][b2][s2][tid];
                }
                vsh[(s << 10) + tid] = __float2half_rn(1.0f / sum);
            }
        }
        if (tid < 112) us_f[tid] = 0.0f;
        __syncthreads();

        // ---- row phase: us_f[i] = sum_j P_ij * v_j  (HMMA) ----
        for (int s = 0; s < nseg; s++) {
            const int s_lo = s ? s_break : 0;
            const int s_hi = s ? nrows : s_break;
            const int len = s_hi - s_lo;
            const int ntile = (len + 15) >> 4;
            if (mt < ntile) {
                float c[4] = {0.f, 0.f, 0.f, 0.f};
                const int rbase = min(s_lo + mt * 16 + l15, s_hi - 1);
                const __half* vs = vsh + (s << 10);
                #pragma unroll 4
                for (int kc = kq * 16; kc < kq * 16 + 16; kc++) {
                    const int k0 = kc * 16;
                    unsigned a0, a1, a2, a3;
                    ldsm4(a0, a1, a2, a3, ps_base + sw_off(rbase, (k0 >> 3) + l16));
                    unsigned aa[4] = {a0, a1, a2, a3};
                    unsigned b0 = *(const unsigned*)(vs + k0 + c2);
                    unsigned b1 = *(const unsigned*)(vs + k0 + c2 + 8);
                    mma16816(c, aa, b0, b1);
                }
                if ((lane & 3) == 0) {
                    if (mt * 16 + g < len)
                        atomicAdd(&us_f[s_lo + mt * 16 + g], c[0]);
                    if (mt * 16 + 8 + g < len)
                        atomicAdd(&us_f[s_lo + mt * 16 + 8 + g], c[2]);
                }
            }
        }
        __syncthreads();

        // ---- stage u as fp16, zero-padded per segment ----
        if (tid < 128) {
            float u0 = (tid < s_break) ? (1.0f / us_f[tid]) : 0.0f;
            float u1 = (tid >= s_break && tid < nrows) ? (1.0f / us_f[tid]) : 0.0f;
            ush0[tid] = __float2half_rn(u0);
            ush1[tid] = __float2half_rn(u1);
        }
        __syncthreads();

        // ---- col phase: partial_j = sum_i u_i P_ij  (HMMA, private STG) ----
        const int j0a = warp * 16, j0b = (warp + 32) * 16;
        for (int s = 0; s < nseg; s++) {
            const __half* us = s ? ush1 : ush0;
            const int kt_lo = (s ? s_break : 0) >> 4;
            const int kt_hi = ((s ? nrows : s_break) + 15) >> 4;
            float c00[4] = {0.f,0.f,0.f,0.f}, c01[4] = {0.f,0.f,0.f,0.f};
            float c10[4] = {0.f,0.f,0.f,0.f}, c11[4] = {0.f,0.f,0.f,0.f};
            for (int kt = kt_lo; kt < kt_hi; kt++) {
                const int k0 = kt * 16;
                unsigned a01 = *(const unsigned*)(us + k0 + c2);
                unsigned a23 = *(const unsigned*)(us + k0 + c2 + 8);
                unsigned aa[4] = {a01, a01, a23, a23};
                const int rrow = min(k0 + l15, nrows - 1);
                unsigned b0, b1, b2, b3;
                ldsm4t(b0, b1, b2, b3, ps_base + sw_off(rrow, (j0a >> 3) + l16));
                mma16816(c00, aa, b0, b1);
                mma16816(c01, aa, b2, b3);
                ldsm4t(b0, b1, b2, b3, ps_base + sw_off(rrow, (j0b >> 3) + l16));
                mma16816(c10, aa, b0, b1);
                mma16816(c11, aa, b2, b3);
            }
            if (g == 0) {
                float* pw = g_part[wbuf][blk][s];
                float2 f;
                f.x = c00[0]; f.y = c00[1]; *(float2*)(pw + j0a + c2)     = f;
                f.x = c01[0]; f.y = c01[1]; *(float2*)(pw + j0a + 8 + c2) = f;
                f.x = c10[0]; f.y = c10[1]; *(float2*)(pw + j0b + c2)     = f;
                f.x = c11[0]; f.y = c11[1]; *(float2*)(pw + j0b + 8 + c2) = f;
            }
        }

        gsync_flag(it);
    }

    // ---- tail: g_ur, final v, g_vt = v_j * V^T ----
    for (int i = tid; i < nrows; i += 1024)
        g_ur[r0 + i] = 1.0f / us_f[i];
    __syncthreads();
    if (tid < nrows) {
        const int gr = r0 + tid, bh = gr >> 10, j = gr & 1023;
        const int b_lo = blk_of(bh << 10), b_hi = blk_of((bh << 10) + 1023);
        float sum = 0.0f;
        for (int b2 = b_lo; b2 <= b_hi; b2++) {
            const int s2 = ((row_start(b2) >> 10) == bh) ? 0 : 1;
            sum += g_part[(NITERS - 1) & 1][b2][s2][j];
        }
        us_f[tid] = 1.0f / sum;          // reuse as v_local
    }
    __syncthreads();
    for (int d = warp; d < 64; d += 32) {
        for (int i = lane; i < nrows; i += 32) {
            const int gr = r0 + i, bh = gr >> 10, j = gr & 1023;
            float vv = g_v[(bh << 16) + (j << 6) + d];
            g_vt[(bh << 16) + (d << 10) + j] = __float2half_rn(us_f[i] * vv);
        }
    }
}

// ============================================================================
extern "C" void kernel_launch(void* const* d_in, const int* in_sizes, int n_in,
                              void* d_out, int out_size)
{
    const float* x  = (const float*)d_in[0];
    const float* Wq = (const float*)d_in[1];
    const float* bq = (const float*)d_in[2];
    const float* Wk = (const float*)d_in[3];
    const float* bk = (const float*)d_in[4];
    const float* Wv = (const float*)d_in[5];
    const float* bv = (const float*)d_in[6];
    const float* Wo = (const float*)d_in[7];
    const float* bo = (const float*)d_in[8];
    float* out = (float*)d_out;

    static int smem_set = 0;
    if (!smem_set) {
        cudaFuncSetAttribute(sinkhorn_tc,
                             cudaFuncAttributeMaxDynamicSharedMemorySize, SMEM_SZ);
        smem_set = 1;
    }

    conv_all<<<6145, 256>>>(x, Wq, Wk, Wv, Wo);              // 1 (also resets barrier)
    qkv_h_kernel<<<dim3(8, 16, 3), 256>>>(bq, bk, bv);       // 2
    p_h_kernel<<<dim3(16, 8, NBH), 256>>>();                 // 3
    sinkhorn_tc<<<NBLOCKS, 1024, SMEM_SZ>>>();               // 4  <- profiled
    attnv_h_kernel<<<dim3(1, 8, NBH), 256>>>();              // 5
    out_h_kernel<<<dim3(16, 16, 1), 256>>>(bo, out);         // 6
}